// round 16
// baseline (speedup 1.0000x reference)
#include <cuda_runtime.h>
#include <cuda_fp16.h>
#include <math.h>
#include <stdint.h>

#define B_TOT 8192

// ============================================================================
// Device globals.  A: row-major fp16 (known-good R12 layout).
// B: PRE-SWIZZLED 32KB chunk images (exact smem image -> one bulk copy each).
// ============================================================================
__device__ __align__(16) __half g_B_ecc[7 * 16384];   // 7 chunks x 32KB
__device__ __align__(16) __half g_B_err[5 * 16384];
__device__ __align__(16) __half g_WeT[64 * 64];       // We^T fp16 [n][k]
__device__ __align__(16) __half g_Ah_ecc[B_TOT * 448];
__device__ __align__(16) __half g_Ah_err[B_TOT * 320];
__device__ __align__(16) __half g_Ah_ehr[B_TOT * 64];
__device__ float g_bias_part[28 * 256];

// ---------------------------------------------------------------------------
#define MMA16816(d, a, b0_, b1_) \
    asm volatile( \
        "mma.sync.aligned.m16n8k16.row.col.f32.f16.f16.f32 " \
        "{%0,%1,%2,%3}, {%4,%5,%6,%7}, {%8,%9}, {%0,%1,%2,%3};" \
        : "+f"((d)[0]), "+f"((d)[1]), "+f"((d)[2]), "+f"((d)[3]) \
        : "r"((a)[0]), "r"((a)[1]), "r"((a)[2]), "r"((a)[3]), \
          "r"(b0_), "r"(b1_))

#define LDSM_X4(r0, r1, r2, r3, addr) \
    asm volatile( \
        "ldmatrix.sync.aligned.m8n8.x4.shared.b16 {%0,%1,%2,%3}, [%4];" \
        : "=r"(r0), "=r"(r1), "=r"(r2), "=r"(r3) : "r"(addr))

#define CP_ASYNC16(dst, src) \
    asm volatile("cp.async.cg.shared.global [%0], [%1], 16;" \
        :: "r"(dst), "l"(src) : "memory")
#define CP_COMMIT() asm volatile("cp.async.commit_group;" ::: "memory")
#define CP_WAIT0()  asm volatile("cp.async.wait_group 0;" ::: "memory")
#define CP_WAIT1()  asm volatile("cp.async.wait_group 1;" ::: "memory")

#define CP_BULK(dst, src, bytes, mbar) \
    asm volatile( \
        "cp.async.bulk.shared::cta.global.mbarrier::complete_tx::bytes " \
        "[%0], [%1], %2, [%3];" \
        :: "r"(dst), "l"(src), "r"(bytes), "r"(mbar) : "memory")

#define MBARRIER_INIT(mbar, count) \
    asm volatile("mbarrier.init.shared.b64 [%0], %1;" \
        :: "r"((uint32_t)(mbar)), "r"((uint32_t)(count)) : "memory")
#define MBARRIER_EXPECT_TX(mbar, bytes) \
    asm volatile("mbarrier.arrive.expect_tx.shared.b64 _, [%0], %1;" \
        :: "r"((uint32_t)(mbar)), "r"((uint32_t)(bytes)) : "memory")
#define MBARRIER_WAIT_PARITY(mbar_addr, phase_parity) do { \
    uint32_t _mbar = (uint32_t)(mbar_addr); \
    uint32_t _parity = (uint32_t)(phase_parity); \
    uint32_t _done; \
    asm volatile( \
        "{\n\t.reg .pred p;\n\t" \
        "mbarrier.try_wait.parity.acquire.cta.shared::cta.b64 p, [%1], %2;\n\t" \
        "selp.b32 %0, 1, 0, p;\n\t}" \
        : "=r"(_done) : "r"(_mbar), "r"(_parity) : "memory"); \
    if (!_done) { \
        asm volatile( \
            "{\n\t.reg .pred P1;\n\t" \
            "WAIT_LOOP_%=:\n\t" \
            "mbarrier.try_wait.parity.acquire.cta.shared::cta.b64 P1, [%0], %1, 0x989680;\n\t" \
            "@P1 bra.uni WAIT_DONE_%=;\n\t" \
            "bra.uni WAIT_LOOP_%=;\n\t" \
            "WAIT_DONE_%=:\n\t}" \
            :: "r"(_mbar), "r"(_parity) : "memory"); \
    } \
} while(0)

#define SWZ(off) ((off) ^ (((off) >> 3) & 0x70))

__device__ __forceinline__ uint32_t smem_to_u32(const void* p) {
    uint32_t a;
    asm("{ .reg .u64 t; cvta.to.shared.u64 t, %1; cvt.u32.u64 %0, t; }"
        : "=r"(a) : "l"(p));
    return a;
}
__device__ __forceinline__ uint32_t pack_hi16(float a, float b) {
    return (uint32_t)__half_as_ushort(__float2half(a)) |
           ((uint32_t)__half_as_ushort(__float2half(b)) << 16);
}
__device__ __forceinline__ float tanh_fast(float x) {
    float y;
    asm("tanh.approx.f32 %0, %1;" : "=f"(y) : "f"(x));
    return y;
}

// ============================================================================
// K1: merged precompute + fp16 conversions.
// IDENTICAL to R15 except the R-block B writes target chunk images
// (same scattered-store cost; only the address formula changes).
// ============================================================================
__global__ __launch_bounds__(256) void precompute(
    const float* __restrict__ ecc, const float* __restrict__ err,
    const float* __restrict__ ehr,
    const float* __restrict__ wt_ecc, const float* __restrict__ bt_ecc,
    const float* __restrict__ wt_err, const float* __restrict__ bt_err,
    const float* __restrict__ W0_ecc, const float* __restrict__ W1_ecc,
    const float* __restrict__ b_ecc,
    const float* __restrict__ W0_err, const float* __restrict__ W1_err,
    const float* __restrict__ b_err,
    const float* __restrict__ Wp_ecc, const float* __restrict__ bp_ecc,
    const float* __restrict__ Wp_err, const float* __restrict__ bp_err,
    const float* __restrict__ We)
{
    const int blk = blockIdx.x;
    const int t   = threadIdx.x;

    if (blk < 140) {
        // ------------------- R rows with inline Weff -------------------
        const int graph = (blk >= 80);
        const int rel   = graph ? blk - 80 : blk;
        const int u     = rel / 5;
        const int tpg   = rel % 5;
        const int V     = graph ? 12 : 16;
        const int K     = graph ? 300 : 400;
        const int KP    = graph ? 320 : 448;
        const float* wt = graph ? wt_err : wt_ecc;
        const float* W0 = graph ? W0_err : W0_ecc;
        const float* W1 = graph ? W1_err : W1_ecc;
        const float* Wp = graph ? Wp_err : Wp_ecc;
        char* B = (char*)(graph ? g_B_err : g_B_ecc);

        __shared__ float wts[96];
        __shared__ float w0s[5 * 64];
        __shared__ float w1s[5 * 64];
        if (t < 96) wts[t] = wt[t];
        __syncthreads();

        for (int idx = t; idx < 320; idx += 256) {
            const int j = idx >> 6, g = idx & 63;
            const int tp = tpg * 5 + j;
            float s0 = 0.f, s1 = 0.f;
            #pragma unroll 4
            for (int c = 0; c < 32; c++) {
                #pragma unroll
                for (int k = 0; k < 3; k++) {
                    const int tt = tp - k + 1;
                    if (tt >= 0 && tt < 25) {
                        const float w = wts[c * 3 + k];
                        s0 = fmaf(w, W0[(c * 25 + tt) * 64 + g], s0);
                        s1 = fmaf(w, W1[(c * 25 + tt) * 64 + g], s1);
                    }
                }
            }
            w0s[idx] = s0;
            w1s[idx] = -0.5f * s1;
        }
        __syncthreads();

        const int h  = t;                 // output column n (0..255)
        const int up = (u + 1) % V;
        const int um = (u + V - 1) % V;

        float acc[5] = {0.f, 0.f, 0.f, 0.f, 0.f};
        const float* WpU = Wp + (size_t)(u  * 64) * 256 + h;
        const float* WpP = Wp + (size_t)(up * 64) * 256 + h;
        const float* WpM = Wp + (size_t)(um * 64) * 256 + h;

        #pragma unroll 4
        for (int gg = 0; gg < 64; gg++) {
            const float wp_u = WpU[gg * 256];
            const float wp_s = WpP[gg * 256] + WpM[gg * 256];
            #pragma unroll
            for (int j = 0; j < 5; j++) {
                acc[j] = fmaf(w0s[j * 64 + gg], wp_u, acc[j]);
                acc[j] = fmaf(w1s[j * 64 + gg], wp_s, acc[j]);
            }
        }

        // write into 32KB pre-swizzled chunk images: element (n=h, k)
        #pragma unroll
        for (int j = 0; j < 5; j++) {
            const int k = u * 25 + tpg * 5 + j;
            const int c = k >> 6, kk = k & 63;
            const uint32_t off = SWZ((uint32_t)(h * 128 + kk * 2));
            *(__half*)(B + (size_t)c * 32768 + off) = __float2half(acc[j]);
        }
        if (u == 0 && tpg == 0) {
            for (int k = K; k < KP; k++) {
                const int c = k >> 6, kk = k & 63;
                const uint32_t off = SWZ((uint32_t)(h * 128 + kk * 2));
                *(__half*)(B + (size_t)c * 32768 + off) =
                    __ushort_as_half((unsigned short)0);
            }
        }
    } else if (blk < 168) {
        // ------------------- c0 + bias_part -------------------
        const int rel   = blk - 140;
        const int graph = (rel >= 16);
        const int u     = graph ? rel - 16 : rel;
        const float* bt = graph ? bt_err : bt_ecc;
        const float* W0 = graph ? W0_err : W0_ecc;
        const float* W1 = graph ? W1_err : W1_ecc;
        const float* bb = graph ? b_err  : b_ecc;
        const float* Wp = graph ? Wp_err : Wp_ecc;
        const float* bp = graph ? bp_err : bp_ecc;

        __shared__ float part[256];
        __shared__ float c0s[64];

        const int g = t & 63, cb = (t >> 6) * 8;
        float s = 0.f;
        #pragma unroll
        for (int ci = 0; ci < 8; ci++) {
            const int c = cb + ci;
            float a = 0.f;
            #pragma unroll
            for (int tt = 0; tt < 25; tt++)
                a += W0[(c * 25 + tt) * 64 + g] - W1[(c * 25 + tt) * 64 + g];
            s = fmaf(bt[c], a, s);
        }
        part[t] = s;
        __syncthreads();
        if (t < 64)
            c0s[g] = part[g] + part[64 + g] + part[128 + g] + part[192 + g] + bb[g];
        __syncthreads();

        const int h = t;
        float pbias = (u == 0) ? bp[h] : 0.f;
        const float* WpU = Wp + (size_t)(u * 64) * 256 + h;
        #pragma unroll 8
        for (int gg = 0; gg < 64; gg++)
            pbias = fmaf(c0s[gg], WpU[gg * 256], pbias);
        g_bias_part[((graph ? 16 : 0) + u) * 256 + h] = pbias;
    } else if (blk == 168) {
        // ------------------- We^T fp16 -------------------
        for (int i = t; i < 4096; i += 256) {
            const int n = i >> 6, k = i & 63;
            g_WeT[n * 64 + k] = __float2half(We[k * 64 + n]);
        }
    } else if (blk < 425) {
        // ------------------- ecc -> fp16 row-major, KP=448 -------------------
        const int r0 = (blk - 169) * 32;
        for (int idx = t; idx < 32 * 56; idx += 256) {
            const int row = idx / 56, gg = idx - row * 56;
            uint4 v = make_uint4(0u, 0u, 0u, 0u);
            if (gg < 50) {
                const float* s = ecc + (size_t)(r0 + row) * 400 + gg * 8;
                const float4 a = *(const float4*)s;
                const float4 b = *(const float4*)(s + 4);
                v.x = pack_hi16(a.x, a.y); v.y = pack_hi16(a.z, a.w);
                v.z = pack_hi16(b.x, b.y); v.w = pack_hi16(b.z, b.w);
            }
            *(uint4*)(g_Ah_ecc + (size_t)(r0 + row) * 448 + gg * 8) = v;
        }
    } else if (blk < 681) {
        // ------------------- err -> fp16 row-major, KP=320 -------------------
        const int r0 = (blk - 425) * 32;
        for (int idx = t; idx < 32 * 40; idx += 256) {
            const int row = idx / 40, gg = idx - row * 40;
            uint4 v = make_uint4(0u, 0u, 0u, 0u);
            if (gg < 37) {
                const float* s = err + (size_t)(r0 + row) * 300 + gg * 8;
                const float4 a = *(const float4*)s;
                const float4 b = *(const float4*)(s + 4);
                v.x = pack_hi16(a.x, a.y); v.y = pack_hi16(a.z, a.w);
                v.z = pack_hi16(b.x, b.y); v.w = pack_hi16(b.z, b.w);
            } else if (gg == 37) {
                const float* s = err + (size_t)(r0 + row) * 300 + 296;
                v.x = pack_hi16(s[0], s[1]); v.y = pack_hi16(s[2], s[3]);
            }
            *(uint4*)(g_Ah_err + (size_t)(r0 + row) * 320 + gg * 8) = v;
        }
    } else {
        // ------------------- ehr -> fp16 -------------------
        const int r0 = (blk - 681) * 128;
        for (int idx = t; idx < 128 * 8; idx += 256) {
            const int row = idx >> 3, gg = idx & 7;
            const float* s = ehr + (size_t)(r0 + row) * 64 + gg * 8;
            const float4 a = *(const float4*)s;
            const float4 b = *(const float4*)(s + 4);
            uint4 v;
            v.x = pack_hi16(a.x, a.y); v.y = pack_hi16(a.z, a.w);
            v.z = pack_hi16(b.x, b.y); v.w = pack_hi16(b.z, b.w);
            *(uint4*)(g_Ah_ehr + (size_t)(r0 + row) * 64 + gg * 8) = v;
        }
    }
}

// ============================================================================
// K2: FUSED GEMM + ehr-MMA + epilogue.  128 blocks x 64 rows, 512 threads.
// HYBRID staging: A via 512 per-thread cp.async (1 granule/thread/chunk),
// B via ONE cp.async.bulk (32KB image) -> per-chunk issue floor drops ~5x.
// Unified 12-chunk pipeline over both graphs, 3 stages.
// ============================================================================
#define A_OFF        0
#define B_OFF        8192
#define STAGE_SZ     40960
#define EHRP_OFF     40960
#define STASH_E_OFF  122880
#define STASH_STRIDE 264
#define STASH_R_OFF  156672
#define BIAS_E_OFF   190464
#define BIAS_R_OFF   191488
#define MBAR_OFF     192512
#define FUSED_SMEM   192576

__global__ __launch_bounds__(512, 1) void fused_kernel(
    const float* __restrict__ Wa, const float* __restrict__ ba,
    const float* __restrict__ be,
    const float* __restrict__ Wf2, const float* __restrict__ bf2,
    float* __restrict__ out)
{
    extern __shared__ char dsm[];
    const uint32_t sb = smem_to_u32(dsm);
    const int tid = threadIdx.x, lane = tid & 31, wid = tid >> 5;
    const int bm = blockIdx.x;

    if (tid == 0) {
        MBARRIER_INIT(sb + MBAR_OFF,      1);
        MBARRIER_INIT(sb + MBAR_OFF + 8,  1);
        MBARRIER_INIT(sb + MBAR_OFF + 16, 1);
    }
    if (tid < 256) {
        float s = 0.f;
        #pragma unroll
        for (int u = 0; u < 16; u++) s += g_bias_part[u * 256 + tid];
        ((float*)(dsm + BIAS_E_OFF))[tid] = s;
        s = 0.f;
        #pragma unroll
        for (int u = 0; u < 12; u++) s += g_bias_part[(16 + u) * 256 + tid];
        ((float*)(dsm + BIAS_R_OFF))[tid] = s;
    }
    __syncthreads();

    const int warp_m = wid & 3;      // 16 rows each
    const int warp_n = wid >> 2;     // 64 cols each
    const int sub = lane >> 3, i8 = lane & 7;
    const int arow = tid >> 3, agrn = tid & 7;   // A-staging mapping

    // global chunk cc in [0,12): graph = cc>=7
    auto issueA = [&](int cc) {
        const uint32_t base = sb + (cc % 3) * STAGE_SZ;
        const __half* Ap;
        int KP, c;
        if (cc < 7) { Ap = g_Ah_ecc; KP = 448; c = cc; }
        else        { Ap = g_Ah_err; KP = 320; c = cc - 7; }
        const __half* src = Ap + (size_t)(bm * 64 + arow) * KP + c * 64 + agrn * 8;
        const uint32_t off = (uint32_t)(arow * 8 + (agrn ^ (arow & 7))) * 16u;
        CP_ASYNC16(base + A_OFF + off, (const void*)src);
        CP_COMMIT();
    };
    auto issueB = [&](int cc) {   // tid 0 only
        const uint32_t mbar = sb + MBAR_OFF + (cc % 3) * 8;
        const uint32_t base = sb + (cc % 3) * STAGE_SZ;
        const char* src = (cc < 7)
            ? (const char*)g_B_ecc + (size_t)cc * 32768
            : (const char*)g_B_err + (size_t)(cc - 7) * 32768;
        MBARRIER_EXPECT_TX(mbar, 32768u);
        CP_BULK(base + B_OFF, src, 32768u, mbar);
    };

    issueA(0);
    if (tid == 0) issueB(0);
    issueA(1);
    if (tid == 0) issueB(1);

    float acc[8][4];
    #pragma unroll
    for (int ni = 0; ni < 8; ni++)
        #pragma unroll
        for (int q = 0; q < 4; q++) acc[ni][q] = 0.f;

    const int g8 = lane >> 2, tg = lane & 3;

    for (int cc = 0; cc < 12; cc++) {
        if (cc + 1 < 12) { CP_WAIT1(); } else { CP_WAIT0(); }
        MBARRIER_WAIT_PARITY(sb + MBAR_OFF + (cc % 3) * 8, (cc / 3) & 1);
        __syncthreads();                 // everyone done with chunk cc-1
        if (cc + 2 < 12) {
            issueA(cc + 2);
            if (tid == 0) issueB(cc + 2);
        }

        const uint32_t base = sb + (cc % 3) * STAGE_SZ;
        #pragma unroll
        for (int ks = 0; ks < 4; ks++) {
            uint32_t ah[4];
            {
                const int ar = warp_m * 16 + i8 + (sub & 1) * 8;
                const int akg = ks * 2 + (sub >> 1);
                const uint32_t off =
                    (uint32_t)(ar * 64 + ((akg ^ (ar & 7)) * 8)) * 2u;
                LDSM_X4(ah[0], ah[1], ah[2], ah[3], base + A_OFF + off);
            }
            #pragma unroll
            for (int p = 0; p < 4; p++) {
                const int nn = warp_n * 64 + p * 16 + i8 + (sub >> 1) * 8;
                const int bkg = ks * 2 + (sub & 1);
                const uint32_t off =
                    (uint32_t)(nn * 64 + ((bkg ^ (nn & 7)) * 8)) * 2u;
                uint32_t b0, b1, b2, b3;
                LDSM_X4(b0, b1, b2, b3, base + B_OFF + off);
                MMA16816(acc[2 * p],     ah, b0, b1);
                MMA16816(acc[2 * p + 1], ah, b2, b3);
            }
        }

        if (cc == 6 || cc == 11) {
            // graph boundary: write stash (+bias) and reset accumulators
            const int graph = (cc == 11);
            __half* stash = (__half*)(dsm + (graph ? STASH_R_OFF : STASH_E_OFF));
            const float* bias_s =
                (const float*)(dsm + (graph ? BIAS_R_OFF : BIAS_E_OFF));
            const int row0 = warp_m * 16 + g8;
            #pragma unroll
            for (int ni = 0; ni < 8; ni++) {
                const int col = warp_n * 64 + ni * 8 + tg * 2;
                const float b0 = bias_s[col], b1 = bias_s[col + 1];
                *(__half2*)(stash + row0 * STASH_STRIDE + col) =
                    __floats2half2_rn(acc[ni][0] + b0, acc[ni][1] + b1);
                *(__half2*)(stash + (row0 + 8) * STASH_STRIDE + col) =
                    __floats2half2_rn(acc[ni][2] + b0, acc[ni][3] + b1);
                #pragma unroll
                for (int q = 0; q < 4; q++) acc[ni][q] = 0.f;
            }
        }
    }
    __syncthreads();

    // ---- ehr mini-GEMM: ehrp = relu(ehr @ We + be) ----
    {
        {
            const __half* src = g_Ah_ehr + (size_t)(bm * 64 + arow) * 64 + agrn * 8;
            const uint32_t off = (uint32_t)(arow * 8 + (agrn ^ (arow & 7))) * 16u;
            CP_ASYNC16(sb + A_OFF + off, (const void*)src);
        }
        {
            const __half* src = g_WeT + (size_t)arow * 64 + agrn * 8;
            const uint32_t off = (uint32_t)(arow * 8 + (agrn ^ (arow & 7))) * 16u;
            CP_ASYNC16(sb + B_OFF + off, (const void*)src);
        }
        CP_COMMIT();
        CP_WAIT0();
        __syncthreads();

        float accH[2][4];
        #pragma unroll
        for (int ni = 0; ni < 2; ni++)
            #pragma unroll
            for (int q = 0; q < 4; q++) accH[ni][q] = 0.f;

        #pragma unroll
        for (int ks = 0; ks < 4; ks++) {
            uint32_t ah[4];
            {
                const int ar = warp_m * 16 + i8 + (sub & 1) * 8;
                const int akg = ks * 2 + (sub >> 1);
                const uint32_t off =
                    (uint32_t)(ar * 64 + ((akg ^ (ar & 7)) * 8)) * 2u;
                LDSM_X4(ah[0], ah[1], ah[2], ah[3], sb + A_OFF + off);
            }
            const int nn = warp_n * 16 + i8 + (sub >> 1) * 8;
            const int bkg = ks * 2 + (sub & 1);
            const uint32_t off =
                (uint32_t)(nn * 64 + ((bkg ^ (nn & 7)) * 8)) * 2u;
            uint32_t b0, b1, b2, b3;
            LDSM_X4(b0, b1, b2, b3, sb + B_OFF + off);
            MMA16816(accH[0], ah, b0, b1);
            MMA16816(accH[1], ah, b2, b3);
        }

        float* ehrp = (float*)(dsm + EHRP_OFF);
        {
            const int row0 = warp_m * 16 + g8;
            #pragma unroll
            for (int ni = 0; ni < 2; ni++) {
                const int col = warp_n * 16 + ni * 8 + tg * 2;
                const float b0 = __ldg(be + col), b1 = __ldg(be + col + 1);
                ehrp[row0 * 64 + col]       = fmaxf(accH[ni][0] + b0, 0.f);
                ehrp[row0 * 64 + col + 1]   = fmaxf(accH[ni][1] + b1, 0.f);
                ehrp[(row0 + 8) * 64 + col] = fmaxf(accH[ni][2] + b0, 0.f);
                ehrp[(row0 + 8) * 64 + col + 1] =
                    fmaxf(accH[ni][3] + b1, 0.f);
            }
        }
    }
    __syncthreads();

    // ---- epilogue (16 warps x 4 rows, all from smem) ----
    const __half* stash_e = (const __half*)(dsm + STASH_E_OFF);
    const __half* stash_r = (const __half*)(dsm + STASH_R_OFF);
    const float* ehrp     = (const float*)(dsm + EHRP_OFF);
    const float ba0 = ba[0], bf0 = bf2[0];
    float wa[8], wf[8];
    #pragma unroll
    for (int j = 0; j < 8; j++) {
        wa[j] = Wa[lane + 32 * j];
        wf[j] = Wf2[lane + 32 * j];
    }
    const float wfe0 = Wf2[256 + lane], wfe1 = Wf2[256 + lane + 32];

    #pragma unroll
    for (int q = 0; q < 4; q++) {
        const int row = wid * 4 + q;
        float e[8], r[8];
        #pragma unroll
        for (int j = 0; j < 8; j++) {
            e[j] = __half2float(stash_e[row * STASH_STRIDE + lane + 32 * j]);
            r[j] = __half2float(stash_r[row * STASH_STRIDE + lane + 32 * j]);
        }
        const float o0 = ehrp[row * 64 + lane];
        const float o1 = ehrp[row * 64 + lane + 32];

        float s = 0.f;
        #pragma unroll
        for (int j = 0; j < 8; j++)
            s = fmaf(tanh_fast(e[j] + r[j]), wa[j], s);
        #pragma unroll
        for (int off = 16; off > 0; off >>= 1)
            s += __shfl_xor_sync(0xffffffffu, s, off);
        const float attn = 1.f / (1.f + __expf(-(s + ba0)));

        float v = o0 * wfe0 + o1 * wfe1;
        #pragma unroll
        for (int j = 0; j < 8; j++) {
            const float f = attn * e[j] + (1.f - attn) * r[j];
            v = fmaf(fmaxf(f, 0.f), wf[j], v);
        }
        #pragma unroll
        for (int off = 16; off > 0; off >>= 1)
            v += __shfl_xor_sync(0xffffffffu, v, off);
        if (lane == 0)
            out[bm * 64 + row] = 1.f / (1.f + __expf(-(v + bf0)));
    }
}

// ============================================================================
extern "C" void kernel_launch(void* const* d_in, const int* in_sizes, int n_in,
                              void* d_out, int out_size) {
    const float* ecc    = (const float*)d_in[0];
    const float* err    = (const float*)d_in[1];
    const float* ehr    = (const float*)d_in[2];
    const float* wt_ecc = (const float*)d_in[3];
    const float* bt_ecc = (const float*)d_in[4];
    const float* wt_err = (const float*)d_in[5];
    const float* bt_err = (const float*)d_in[6];
    const float* W0_ecc = (const float*)d_in[7];
    const float* W1_ecc = (const float*)d_in[8];
    const float* b_ecc  = (const float*)d_in[9];
    const float* W0_err = (const float*)d_in[10];
    const float* W1_err = (const float*)d_in[11];
    const float* b_err  = (const float*)d_in[12];
    const float* Wp_ecc = (const float*)d_in[13];
    const float* bp_ecc = (const float*)d_in[14];
    const float* Wp_err = (const float*)d_in[15];
    const float* bp_err = (const float*)d_in[16];
    const float* Wa     = (const float*)d_in[17];
    const float* ba     = (const float*)d_in[18];
    const float* We     = (const float*)d_in[19];
    const float* be     = (const float*)d_in[20];
    const float* Wf2    = (const float*)d_in[21];
    const float* bf2    = (const float*)d_in[22];

    cudaFuncSetAttribute(fused_kernel,
                         cudaFuncAttributeMaxDynamicSharedMemorySize, FUSED_SMEM);

    precompute<<<745, 256>>>(ecc, err, ehr,
                             wt_ecc, bt_ecc, wt_err, bt_err,
                             W0_ecc, W1_ecc, b_ecc, W0_err, W1_err, b_err,
                             Wp_ecc, bp_ecc, Wp_err, bp_err, We);
    fused_kernel<<<128, 512, FUSED_SMEM>>>(Wa, ba, be, Wf2, bf2,
                                           (float*)d_out);
}

// round 17
// speedup vs baseline: 1.1898x; 1.1898x over previous
#include <cuda_runtime.h>
#include <cuda_fp16.h>
#include <math.h>
#include <stdint.h>

#define B_TOT 8192

// ============================================================================
// Device globals. B: row-major fp16 [256][KP] (known-good). No A staging
// buffers — A is converted fp32->fp16 inline in the fused kernel.
// ============================================================================
__device__ __align__(16) __half g_B_ecc[256 * 448];
__device__ __align__(16) __half g_B_err[256 * 320];
__device__ __align__(16) __half g_WeT[64 * 64];       // We^T fp16 [n][k]
__device__ float g_bias_part[28 * 256];

// ---------------------------------------------------------------------------
#define MMA16816(d, a, b0_, b1_) \
    asm volatile( \
        "mma.sync.aligned.m16n8k16.row.col.f32.f16.f16.f32 " \
        "{%0,%1,%2,%3}, {%4,%5,%6,%7}, {%8,%9}, {%0,%1,%2,%3};" \
        : "+f"((d)[0]), "+f"((d)[1]), "+f"((d)[2]), "+f"((d)[3]) \
        : "r"((a)[0]), "r"((a)[1]), "r"((a)[2]), "r"((a)[3]), \
          "r"(b0_), "r"(b1_))

#define LDSM_X4(r0, r1, r2, r3, addr) \
    asm volatile( \
        "ldmatrix.sync.aligned.m8n8.x4.shared.b16 {%0,%1,%2,%3}, [%4];" \
        : "=r"(r0), "=r"(r1), "=r"(r2), "=r"(r3) : "r"(addr))

#define STS128(r0, r1, r2, r3, addr) \
    asm volatile("st.shared.v4.b32 [%0], {%1, %2, %3, %4};" \
        :: "r"(addr), "r"(r0), "r"(r1), "r"(r2), "r"(r3) : "memory")

#define CP_ASYNC16(dst, src) \
    asm volatile("cp.async.cg.shared.global [%0], [%1], 16;" \
        :: "r"(dst), "l"(src) : "memory")
#define CP_COMMIT() asm volatile("cp.async.commit_group;" ::: "memory")
#define CP_WAIT0()  asm volatile("cp.async.wait_group 0;" ::: "memory")
#define CP_WAIT1()  asm volatile("cp.async.wait_group 1;" ::: "memory")

__device__ __forceinline__ uint32_t smem_to_u32(const void* p) {
    uint32_t a;
    asm("{ .reg .u64 t; cvta.to.shared.u64 t, %1; cvt.u32.u64 %0, t; }"
        : "=r"(a) : "l"(p));
    return a;
}
__device__ __forceinline__ uint32_t pack_hi16(float a, float b) {
    return (uint32_t)__half_as_ushort(__float2half(a)) |
           ((uint32_t)__half_as_ushort(__float2half(b)) << 16);
}
__device__ __forceinline__ float tanh_fast(float x) {
    float y;
    asm("tanh.approx.f32 %0, %1;" : "=f"(y) : "f"(x));
    return y;
}

// ============================================================================
// K1: precompute, 169 blocks x 256 thr (NO A conversions anymore).
//  0..139   : R rows (Weff inline) -> row-major B fp16 (+ zero pad K..KP)
//  140..167 : c0 + bias_part        168: We^T fp16
// ============================================================================
__global__ __launch_bounds__(256) void precompute(
    const float* __restrict__ wt_ecc, const float* __restrict__ bt_ecc,
    const float* __restrict__ wt_err, const float* __restrict__ bt_err,
    const float* __restrict__ W0_ecc, const float* __restrict__ W1_ecc,
    const float* __restrict__ b_ecc,
    const float* __restrict__ W0_err, const float* __restrict__ W1_err,
    const float* __restrict__ b_err,
    const float* __restrict__ Wp_ecc, const float* __restrict__ bp_ecc,
    const float* __restrict__ Wp_err, const float* __restrict__ bp_err,
    const float* __restrict__ We)
{
    const int blk = blockIdx.x;
    const int t   = threadIdx.x;

    if (blk < 140) {
        const int graph = (blk >= 80);
        const int rel   = graph ? blk - 80 : blk;
        const int u     = rel / 5;
        const int tpg   = rel % 5;
        const int V     = graph ? 12 : 16;
        const int K     = graph ? 300 : 400;
        const int KP    = graph ? 320 : 448;
        const float* wt = graph ? wt_err : wt_ecc;
        const float* W0 = graph ? W0_err : W0_ecc;
        const float* W1 = graph ? W1_err : W1_ecc;
        const float* Wp = graph ? Wp_err : Wp_ecc;
        __half* B = graph ? g_B_err : g_B_ecc;

        __shared__ float wts[96];
        __shared__ float w0s[5 * 64];
        __shared__ float w1s[5 * 64];
        if (t < 96) wts[t] = wt[t];
        __syncthreads();

        for (int idx = t; idx < 320; idx += 256) {
            const int j = idx >> 6, g = idx & 63;
            const int tp = tpg * 5 + j;
            float s0 = 0.f, s1 = 0.f;
            #pragma unroll 4
            for (int c = 0; c < 32; c++) {
                #pragma unroll
                for (int k = 0; k < 3; k++) {
                    const int tt = tp - k + 1;
                    if (tt >= 0 && tt < 25) {
                        const float w = wts[c * 3 + k];
                        s0 = fmaf(w, W0[(c * 25 + tt) * 64 + g], s0);
                        s1 = fmaf(w, W1[(c * 25 + tt) * 64 + g], s1);
                    }
                }
            }
            w0s[idx] = s0;
            w1s[idx] = -0.5f * s1;
        }
        __syncthreads();

        const int h  = t;
        const int up = (u + 1) % V;
        const int um = (u + V - 1) % V;

        float acc[5] = {0.f, 0.f, 0.f, 0.f, 0.f};
        const float* WpU = Wp + (size_t)(u  * 64) * 256 + h;
        const float* WpP = Wp + (size_t)(up * 64) * 256 + h;
        const float* WpM = Wp + (size_t)(um * 64) * 256 + h;

        #pragma unroll 4
        for (int gg = 0; gg < 64; gg++) {
            const float wp_u = WpU[gg * 256];
            const float wp_s = WpP[gg * 256] + WpM[gg * 256];
            #pragma unroll
            for (int j = 0; j < 5; j++) {
                acc[j] = fmaf(w0s[j * 64 + gg], wp_u, acc[j]);
                acc[j] = fmaf(w1s[j * 64 + gg], wp_s, acc[j]);
            }
        }

        #pragma unroll
        for (int j = 0; j < 5; j++) {
            const int k = u * 25 + tpg * 5 + j;
            B[(size_t)h * KP + k] = __float2half(acc[j]);
        }
        if (u == 0 && tpg == 0) {
            for (int k = K; k < KP; k++)
                B[(size_t)h * KP + k] = __ushort_as_half((unsigned short)0);
        }
    } else if (blk < 168) {
        const int rel   = blk - 140;
        const int graph = (rel >= 16);
        const int u     = graph ? rel - 16 : rel;
        const float* bt = graph ? bt_err : bt_ecc;
        const float* W0 = graph ? W0_err : W0_ecc;
        const float* W1 = graph ? W1_err : W1_ecc;
        const float* bb = graph ? b_err  : b_ecc;
        const float* Wp = graph ? Wp_err : Wp_ecc;
        const float* bp = graph ? bp_err : bp_ecc;

        __shared__ float part[256];
        __shared__ float c0s[64];

        const int g = t & 63, cb = (t >> 6) * 8;
        float s = 0.f;
        #pragma unroll
        for (int ci = 0; ci < 8; ci++) {
            const int c = cb + ci;
            float a = 0.f;
            #pragma unroll
            for (int tt = 0; tt < 25; tt++)
                a += W0[(c * 25 + tt) * 64 + g] - W1[(c * 25 + tt) * 64 + g];
            s = fmaf(bt[c], a, s);
        }
        part[t] = s;
        __syncthreads();
        if (t < 64)
            c0s[g] = part[g] + part[64 + g] + part[128 + g] + part[192 + g] + bb[g];
        __syncthreads();

        const int h = t;
        float pbias = (u == 0) ? bp[h] : 0.f;
        const float* WpU = Wp + (size_t)(u * 64) * 256 + h;
        #pragma unroll 8
        for (int gg = 0; gg < 64; gg++)
            pbias = fmaf(c0s[gg], WpU[gg * 256], pbias);
        g_bias_part[((graph ? 16 : 0) + u) * 256 + h] = pbias;
    } else {
        for (int i = t; i < 4096; i += 256) {
            const int n = i >> 6, k = i & 63;
            g_WeT[n * 64 + k] = __float2half(We[k * 64 + n]);
        }
    }
}

// ============================================================================
// K2: FUSED GEMM + ehr-MMA + epilogue. 128 blocks x 64 rows, 256 thr.
// A converted fp32->fp16 INLINE (regs->pack->STS), B via per-16B cp.async.
// Unified 12-chunk 3-stage pipeline, ONE sync/chunk. K-tail trimming:
// ecc chunk 6 -> kcnt=1, err chunk 4 -> kcnt=3.
// ============================================================================
#define A_OFF        0
#define B_OFF        8192
#define STAGE_SZ     40960
#define EHRP_OFF     40960
#define STASH_E_OFF  122880
#define STASH_STRIDE 264
#define STASH_R_OFF  156672
#define BIAS_E_OFF   190464
#define BIAS_R_OFF   191488
#define FUSED_SMEM   192512

__global__ __launch_bounds__(256, 1) void fused_kernel(
    const float* __restrict__ ecc, const float* __restrict__ err,
    const float* __restrict__ ehr,
    const float* __restrict__ Wa, const float* __restrict__ ba,
    const float* __restrict__ be,
    const float* __restrict__ Wf2, const float* __restrict__ bf2,
    float* __restrict__ out)
{
    extern __shared__ char dsm[];
    const uint32_t sb = smem_to_u32(dsm);
    const int tid = threadIdx.x, lane = tid & 31, wid = tid >> 5;
    const int bm = blockIdx.x;

    {
        float s = 0.f;
        #pragma unroll
        for (int u = 0; u < 16; u++) s += g_bias_part[u * 256 + tid];
        ((float*)(dsm + BIAS_E_OFF))[tid] = s;
        s = 0.f;
        #pragma unroll
        for (int u = 0; u < 12; u++) s += g_bias_part[(16 + u) * 256 + tid];
        ((float*)(dsm + BIAS_R_OFF))[tid] = s;
    }

    const int warp_m = wid & 1, warp_n = wid >> 1;
    const int sub = lane >> 3, i8 = lane & 7;
    const int arow_ld = tid >> 2, aq = tid & 3;   // A: 64 rows x 4 quarters
    float4 va[4];

    // chunk helpers: cc in [0,12), graph = cc>=7
    auto ldgA = [&](int cc) {
        const float* A = (cc < 7) ? ecc : err;
        const int K = (cc < 7) ? 400 : 300;
        const int c = (cc < 7) ? cc : cc - 7;
        const float* Arow = A + (size_t)(bm * 64 + arow_ld) * K;
        #pragma unroll
        for (int j = 0; j < 4; j++) {
            const int k = c * 64 + aq * 16 + j * 4;
            va[j] = (k < K) ? *(const float4*)(Arow + k)
                            : make_float4(0.f, 0.f, 0.f, 0.f);
        }
    };
    auto stsA = [&](int cc) {
        const uint32_t base = sb + (cc % 3) * STAGE_SZ;
        #pragma unroll
        for (int half = 0; half < 2; half++) {
            const float4 p = va[2 * half], q4 = va[2 * half + 1];
            const uint32_t h0 = pack_hi16(p.x, p.y), h1 = pack_hi16(p.z, p.w);
            const uint32_t h2 = pack_hi16(q4.x, q4.y), h3 = pack_hi16(q4.z, q4.w);
            const int g = aq * 2 + half;
            const uint32_t off =
                (uint32_t)(arow_ld * 8 + (g ^ (arow_ld & 7))) * 16u;
            STS128(h0, h1, h2, h3, base + A_OFF + off);
        }
    };
    auto issueB = [&](int cc) {
        const uint32_t base = sb + (cc % 3) * STAGE_SZ;
        const __half* Bp = (cc < 7) ? g_B_ecc : g_B_err;
        const int KP = (cc < 7) ? 448 : 320;
        const int c  = (cc < 7) ? cc : cc - 7;
        #pragma unroll
        for (int it = 0; it < 8; it++) {
            const int idx = tid + it * 256;
            const int row = idx >> 3, g = idx & 7;
            const __half* src = Bp + (size_t)row * KP + c * 64 + g * 8;
            const uint32_t off = (uint32_t)(row * 8 + (g ^ (row & 7))) * 16u;
            CP_ASYNC16(base + B_OFF + off, (const void*)src);
        }
        CP_COMMIT();
    };

    float acc[2][8][4];
    #pragma unroll
    for (int mi = 0; mi < 2; mi++)
        #pragma unroll
        for (int ni = 0; ni < 8; ni++)
            #pragma unroll
            for (int q = 0; q < 4; q++) acc[mi][ni][q] = 0.f;

    // prologue
    issueB(0);
    ldgA(0);
    stsA(0);
    issueB(1);
    ldgA(1);

    const int g8 = lane >> 2, tg = lane & 3;

    for (int cc = 0; cc < 12; cc++) {
        if (cc + 1 < 12) { CP_WAIT1(); } else { CP_WAIT0(); }
        __syncthreads();           // B(cc) + A(cc) visible; stage (cc+1)%3 free
        if (cc + 1 < 12) stsA(cc + 1);
        if (cc + 2 < 12) { ldgA(cc + 2); issueB(cc + 2); }

        const int kcnt = (cc == 6) ? 1 : (cc == 11) ? 3 : 4;
        const uint32_t base = sb + (cc % 3) * STAGE_SZ;
        #pragma unroll 4
        for (int ks = 0; ks < kcnt; ks++) {
            uint32_t ah[2][4];
            #pragma unroll
            for (int mi = 0; mi < 2; mi++) {
                const int ar = warp_m * 32 + mi * 16 + i8 + (sub & 1) * 8;
                const int akg = ks * 2 + (sub >> 1);
                const uint32_t off =
                    (uint32_t)(ar * 64 + ((akg ^ (ar & 7)) * 8)) * 2u;
                LDSM_X4(ah[mi][0], ah[mi][1], ah[mi][2], ah[mi][3],
                        base + A_OFF + off);
            }
            #pragma unroll
            for (int p = 0; p < 4; p++) {
                const int nn = warp_n * 64 + p * 16 + i8 + (sub >> 1) * 8;
                const int bkg = ks * 2 + (sub & 1);
                const uint32_t off =
                    (uint32_t)(nn * 64 + ((bkg ^ (nn & 7)) * 8)) * 2u;
                uint32_t b0, b1, b2, b3;
                LDSM_X4(b0, b1, b2, b3, base + B_OFF + off);
                #pragma unroll
                for (int mi = 0; mi < 2; mi++) {
                    MMA16816(acc[mi][2 * p],     ah[mi], b0, b1);
                    MMA16816(acc[mi][2 * p + 1], ah[mi], b2, b3);
                }
            }
        }

        if (cc == 6 || cc == 11) {
            const int graph = (cc == 11);
            __half* stash = (__half*)(dsm + (graph ? STASH_R_OFF : STASH_E_OFF));
            const float* bias_s =
                (const float*)(dsm + (graph ? BIAS_R_OFF : BIAS_E_OFF));
            #pragma unroll
            for (int mi = 0; mi < 2; mi++) {
                const int row0 = warp_m * 32 + mi * 16 + g8;
                #pragma unroll
                for (int ni = 0; ni < 8; ni++) {
                    const int col = warp_n * 64 + ni * 8 + tg * 2;
                    const float b0 = bias_s[col], b1 = bias_s[col + 1];
                    *(__half2*)(stash + row0 * STASH_STRIDE + col) =
                        __floats2half2_rn(acc[mi][ni][0] + b0,
                                          acc[mi][ni][1] + b1);
                    *(__half2*)(stash + (row0 + 8) * STASH_STRIDE + col) =
                        __floats2half2_rn(acc[mi][ni][2] + b0,
                                          acc[mi][ni][3] + b1);
                    #pragma unroll
                    for (int q = 0; q < 4; q++) acc[mi][ni][q] = 0.f;
                }
            }
        }
    }
    __syncthreads();

    // ---- ehr mini-GEMM: ehrp = relu(ehr @ We + be), A converted inline ----
    {
        {   // A: 64x64 fp32 ehr -> fp16 stage0 A region
            const float* Erow = ehr + (size_t)(bm * 64 + arow_ld) * 64;
            #pragma unroll
            for (int j = 0; j < 4; j++)
                va[j] = *(const float4*)(Erow + aq * 16 + j * 4);
            #pragma unroll
            for (int half = 0; half < 2; half++) {
                const float4 p = va[2 * half], q4 = va[2 * half + 1];
                const uint32_t h0 = pack_hi16(p.x, p.y), h1 = pack_hi16(p.z, p.w);
                const uint32_t h2 = pack_hi16(q4.x, q4.y), h3 = pack_hi16(q4.z, q4.w);
                const int g = aq * 2 + half;
                const uint32_t off =
                    (uint32_t)(arow_ld * 8 + (g ^ (arow_ld & 7))) * 16u;
                STS128(h0, h1, h2, h3, sb + A_OFF + off);
            }
        }
        #pragma unroll
        for (int it = 0; it < 2; it++) {   // B = WeT
            const int idx = tid + it * 256;
            const int row = idx >> 3, g = idx & 7;
            const __half* src = g_WeT + (size_t)row * 64 + g * 8;
            const uint32_t off = (uint32_t)(row * 8 + (g ^ (row & 7))) * 16u;
            CP_ASYNC16(sb + B_OFF + off, (const void*)src);
        }
        CP_COMMIT();
        CP_WAIT0();
        __syncthreads();

        float accH[2][2][4];
        #pragma unroll
        for (int mi = 0; mi < 2; mi++)
            #pragma unroll
            for (int ni = 0; ni < 2; ni++)
                #pragma unroll
                for (int q = 0; q < 4; q++) accH[mi][ni][q] = 0.f;

        #pragma unroll
        for (int ks = 0; ks < 4; ks++) {
            uint32_t ah[2][4];
            #pragma unroll
            for (int mi = 0; mi < 2; mi++) {
                const int ar = warp_m * 32 + mi * 16 + i8 + (sub & 1) * 8;
                const int akg = ks * 2 + (sub >> 1);
                const uint32_t off =
                    (uint32_t)(ar * 64 + ((akg ^ (ar & 7)) * 8)) * 2u;
                LDSM_X4(ah[mi][0], ah[mi][1], ah[mi][2], ah[mi][3],
                        sb + A_OFF + off);
            }
            const int nn = warp_n * 16 + i8 + (sub >> 1) * 8;
            const int bkg = ks * 2 + (sub & 1);
            const uint32_t off =
                (uint32_t)(nn * 64 + ((bkg ^ (nn & 7)) * 8)) * 2u;
            uint32_t b0, b1, b2, b3;
            LDSM_X4(b0, b1, b2, b3, sb + B_OFF + off);
            #pragma unroll
            for (int mi = 0; mi < 2; mi++) {
                MMA16816(accH[mi][0], ah[mi], b0, b1);
                MMA16816(accH[mi][1], ah[mi], b2, b3);
            }
        }

        float* ehrp = (float*)(dsm + EHRP_OFF);
        #pragma unroll
        for (int mi = 0; mi < 2; mi++) {
            const int row0 = warp_m * 32 + mi * 16 + g8;
            #pragma unroll
            for (int ni = 0; ni < 2; ni++) {
                const int col = warp_n * 16 + ni * 8 + tg * 2;
                const float b0 = __ldg(be + col), b1 = __ldg(be + col + 1);
                ehrp[row0 * 64 + col]       = fmaxf(accH[mi][ni][0] + b0, 0.f);
                ehrp[row0 * 64 + col + 1]   = fmaxf(accH[mi][ni][1] + b1, 0.f);
                ehrp[(row0 + 8) * 64 + col] = fmaxf(accH[mi][ni][2] + b0, 0.f);
                ehrp[(row0 + 8) * 64 + col + 1] =
                    fmaxf(accH[mi][ni][3] + b1, 0.f);
            }
        }
    }
    __syncthreads();

    // ---- epilogue (8 warps x 8 rows, all from smem) ----
    const __half* stash_e = (const __half*)(dsm + STASH_E_OFF);
    const __half* stash_r = (const __half*)(dsm + STASH_R_OFF);
    const float* ehrp     = (const float*)(dsm + EHRP_OFF);
    const float ba0 = ba[0], bf0 = bf2[0];
    float wa[8], wf[8];
    #pragma unroll
    for (int j = 0; j < 8; j++) {
        wa[j] = Wa[lane + 32 * j];
        wf[j] = Wf2[lane + 32 * j];
    }
    const float wfe0 = Wf2[256 + lane], wfe1 = Wf2[256 + lane + 32];

    #pragma unroll 2
    for (int q = 0; q < 8; q++) {
        const int row = wid * 8 + q;
        float e[8], r[8];
        #pragma unroll
        for (int j = 0; j < 8; j++) {
            e[j] = __half2float(stash_e[row * STASH_STRIDE + lane + 32 * j]);
            r[j] = __half2float(stash_r[row * STASH_STRIDE + lane + 32 * j]);
        }
        const float o0 = ehrp[row * 64 + lane];
        const float o1 = ehrp[row * 64 + lane + 32];

        float s = 0.f;
        #pragma unroll
        for (int j = 0; j < 8; j++)
            s = fmaf(tanh_fast(e[j] + r[j]), wa[j], s);
        #pragma unroll
        for (int off = 16; off > 0; off >>= 1)
            s += __shfl_xor_sync(0xffffffffu, s, off);
        const float attn = 1.f / (1.f + __expf(-(s + ba0)));

        float v = o0 * wfe0 + o1 * wfe1;
        #pragma unroll
        for (int j = 0; j < 8; j++) {
            const float f = attn * e[j] + (1.f - attn) * r[j];
            v = fmaf(fmaxf(f, 0.f), wf[j], v);
        }
        #pragma unroll
        for (int off = 16; off > 0; off >>= 1)
            v += __shfl_xor_sync(0xffffffffu, v, off);
        if (lane == 0)
            out[bm * 64 + row] = 1.f / (1.f + __expf(-(v + bf0)));
    }
}

// ============================================================================
extern "C" void kernel_launch(void* const* d_in, const int* in_sizes, int n_in,
                              void* d_out, int out_size) {
    const float* ecc    = (const float*)d_in[0];
    const float* err    = (const float*)d_in[1];
    const float* ehr    = (const float*)d_in[2];
    const float* wt_ecc = (const float*)d_in[3];
    const float* bt_ecc = (const float*)d_in[4];
    const float* wt_err = (const float*)d_in[5];
    const float* bt_err = (const float*)d_in[6];
    const float* W0_ecc = (const float*)d_in[7];
    const float* W1_ecc = (const float*)d_in[8];
    const float* b_ecc  = (const float*)d_in[9];
    const float* W0_err = (const float*)d_in[10];
    const float* W1_err = (const float*)d_in[11];
    const float* b_err  = (const float*)d_in[12];
    const float* Wp_ecc = (const float*)d_in[13];
    const float* bp_ecc = (const float*)d_in[14];
    const float* Wp_err = (const float*)d_in[15];
    const float* bp_err = (const float*)d_in[16];
    const float* Wa     = (const float*)d_in[17];
    const float* ba     = (const float*)d_in[18];
    const float* We     = (const float*)d_in[19];
    const float* be     = (const float*)d_in[20];
    const float* Wf2    = (const float*)d_in[21];
    const float* bf2    = (const float*)d_in[22];

    cudaFuncSetAttribute(fused_kernel,
                         cudaFuncAttributeMaxDynamicSharedMemorySize, FUSED_SMEM);

    precompute<<<169, 256>>>(wt_ecc, bt_ecc, wt_err, bt_err,
                             W0_ecc, W1_ecc, b_ecc, W0_err, W1_err, b_err,
                             Wp_ecc, bp_ecc, Wp_err, bp_err, We);
    fused_kernel<<<128, 256, FUSED_SMEM>>>(ecc, err, ehr, Wa, ba, be,
                                           Wf2, bf2, (float*)d_out);
}